// round 2
// baseline (speedup 1.0000x reference)
#include <cuda_runtime.h>

// Involution: B=4, H=W=56, C=256, Cr=64, G=16, Cg=16, K=7, pad=3, stride=1
// Fully fused: reduce-GEMM -> BN -> ReLU -> span-GEMM -> depthwise 49-tap gather.

#define HH 56
#define WWD 56
#define CC 256
#define CR 64
#define NG 16
#define CGC 16
#define KS 7
#define KKT 49
#define THT 4
#define TWT 8
#define NPX 32          // pixels per tile
#define NT 256          // threads per CTA
#define HALO_H (THT + 6)   // 10
#define HALO_W (TWT + 6)   // 14
#define NPOS (HALO_H * HALO_W)  // 140

__global__ __launch_bounds__(NT)
void involution_fused_kernel(
    const float* __restrict__ x,
    const float* __restrict__ w_reduce,
    const float* __restrict__ gamma,
    const float* __restrict__ beta,
    const float* __restrict__ mean,
    const float* __restrict__ var,
    const float* __restrict__ w_span,
    const float* __restrict__ b_span,
    float* __restrict__ out)
{
    __shared__ union {
        struct {
            float xs[NPX][CC];      // 32 KB: x tile, all 256 channels
            float ws[16][CR];       // 4 KB: w_reduce chunk (16 c-rows x 64 d)
        } a;
        struct {
            float wsgT[KKT][68];    // 13.3 KB: w_span slice transposed [k][d], padded
            float kg[NPX][KKT];     // 6.3 KB: kgen for current group
            float xh[NPOS][CGC];    // 9 KB: halo for current group's channels
        } b;
    } u;
    __shared__ float rs[NPX][CR];   // 8 KB: post-BN-ReLU reduced features
    __shared__ float bnS[CR], bnB[CR], bsh[KKT];

    const int t  = threadIdx.x;
    const int w0 = blockIdx.x * TWT;
    const int h0 = blockIdx.y * THT;
    const int bb = blockIdx.z;

    // BN affine fold: y = r*s + (beta - mean*s)
    if (t < CR) {
        float s = gamma[t] * rsqrtf(var[t] + 1e-3f);
        bnS[t] = s;
        bnB[t] = beta[t] - mean[t] * s;
    }

    // ---------------- Phase A1: stage x tile (all channels) ----------------
    {
        for (int i = t; i < NPX * (CC / 4); i += NT) {
            int p  = i >> 6;            // pixel 0..31
            int c4 = i & 63;            // float4 index within channels
            int h = h0 + (p >> 3);
            int w = w0 + (p & 7);
            float4 v = *(const float4*)&x[(((size_t)bb * HH + h) * WWD + w) * CC + c4 * 4];
            *(float4*)&u.a.xs[p][c4 * 4] = v;
        }
    }
    __syncthreads();

    // ---------------- Phase A2: r = xs @ w_reduce, BN, ReLU ----------------
    {
        const int pgrp = t >> 4;              // 0..15 -> pixels 2*pgrp, 2*pgrp+1
        const int p0 = pgrp * 2, p1 = p0 + 1;
        const int d0 = (t & 15) * 4;          // 4 output features per thread
        float acc0[4] = {0.f, 0.f, 0.f, 0.f};
        float acc1[4] = {0.f, 0.f, 0.f, 0.f};

        for (int cb = 0; cb < 16; ++cb) {     // 16 chunks of 16 c-rows
            {
                int row = t >> 4, d4 = t & 15;
                *(float4*)&u.a.ws[row][d4 * 4] =
                    *(const float4*)&w_reduce[((size_t)(cb * 16 + row)) * CR + d4 * 4];
            }
            __syncthreads();
            #pragma unroll
            for (int c = 0; c < 16; ++c) {
                float a0 = u.a.xs[p0][cb * 16 + c];
                float a1 = u.a.xs[p1][cb * 16 + c];
                float4 wv = *(float4*)&u.a.ws[c][d0];
                acc0[0] += a0 * wv.x; acc0[1] += a0 * wv.y;
                acc0[2] += a0 * wv.z; acc0[3] += a0 * wv.w;
                acc1[0] += a1 * wv.x; acc1[1] += a1 * wv.y;
                acc1[2] += a1 * wv.z; acc1[3] += a1 * wv.w;
            }
            __syncthreads();
        }
        #pragma unroll
        for (int j = 0; j < 4; ++j) {
            int d = d0 + j;
            rs[p0][d] = fmaxf(acc0[j] * bnS[d] + bnB[d], 0.f);
            rs[p1][d] = fmaxf(acc1[j] * bnS[d] + bnB[d], 0.f);
        }
    }
    __syncthreads();   // rs ready; union region 'a' dead after this point

    // ---------------- Phase B: per-group span-GEMM + involution ----------------
    for (int g = 0; g < NG; ++g) {
        // B1: halo load (16 channels of this group, zero-padded borders)
        for (int i = t; i < NPOS * 4; i += NT) {
            int pos = i >> 2, q = i & 3;
            int hh = pos / HALO_W, ww = pos - hh * HALO_W;
            int h = h0 + hh - 3, w = w0 + ww - 3;
            float4 v = make_float4(0.f, 0.f, 0.f, 0.f);
            if (h >= 0 && h < HH && w >= 0 && w < WWD)
                v = *(const float4*)&x[(((size_t)bb * HH + h) * WWD + w) * CC + g * CGC + q * 4];
            *(float4*)&u.b.xh[pos][q * 4] = v;
        }
        // B2: stage w_span slice transposed: wsgT[k][d] = w_span[d][g*49+k]
        for (int i = t; i < CR * KKT; i += NT) {
            int d = i / KKT, k = i - d * KKT;
            u.b.wsgT[k][d] = w_span[(size_t)d * (KKT * NG) + g * KKT + k];
        }
        if (t < KKT) bsh[t] = b_span[g * KKT + t];
        __syncthreads();

        // B3: kg[p][k] = rs[p][:] . wsgT[k][:] + bias  (M=32, N=49, K=64)
        if ((t & 7) != 7) {                 // 224 active threads: 32 px * 7 k-groups
            int p  = t >> 3;
            int k0 = (t & 7) * 7;
            float acc[7];
            #pragma unroll
            for (int j = 0; j < 7; ++j) acc[j] = bsh[k0 + j];
            #pragma unroll 4
            for (int d4 = 0; d4 < 16; ++d4) {
                float4 r4 = *(float4*)&rs[p][d4 * 4];
                #pragma unroll
                for (int j = 0; j < 7; ++j) {
                    float4 w4 = *(float4*)&u.b.wsgT[k0 + j][d4 * 4];
                    acc[j] += r4.x * w4.x + r4.y * w4.y + r4.z * w4.z + r4.w * w4.w;
                }
            }
            #pragma unroll
            for (int j = 0; j < 7; ++j) u.b.kg[p][k0 + j] = acc[j];
        }
        __syncthreads();

        // B4: out[p][g*16+cg] = sum_k kg[p][k] * xh[tap(p,k)][cg]
        #pragma unroll
        for (int rep = 0; rep < 2; ++rep) {
            int idx = t + rep * NT;         // 0..511 -> (p, cg)
            int p  = idx >> 4;
            int cg = idx & 15;
            int py = p >> 3, px = p & 7;
            float acc = 0.f;
            #pragma unroll
            for (int kh = 0; kh < KS; ++kh) {
                #pragma unroll
                for (int kw = 0; kw < KS; ++kw) {
                    acc += u.b.kg[p][kh * KS + kw] *
                           u.b.xh[(py + kh) * HALO_W + (px + kw)][cg];
                }
            }
            out[(((size_t)bb * HH + (h0 + py)) * WWD + (w0 + px)) * CC + g * CGC + cg] = acc;
        }
        __syncthreads();   // before next group overwrites xh/kg/wsgT
    }
}

extern "C" void kernel_launch(void* const* d_in, const int* in_sizes, int n_in,
                              void* d_out, int out_size) {
    (void)in_sizes; (void)n_in; (void)out_size;
    const float* x        = (const float*)d_in[0];
    const float* w_reduce = (const float*)d_in[1];
    const float* gamma    = (const float*)d_in[2];
    const float* beta     = (const float*)d_in[3];
    const float* mean     = (const float*)d_in[4];
    const float* var      = (const float*)d_in[5];
    const float* w_span   = (const float*)d_in[6];
    const float* b_span   = (const float*)d_in[7];
    float* out = (float*)d_out;

    dim3 grid(WWD / TWT, HH / THT, 4);   // (7, 14, 4) = 392 CTAs
    involution_fused_kernel<<<grid, NT>>>(x, w_reduce, gamma, beta, mean, var,
                                          w_span, b_span, out);
}

// round 3
// speedup vs baseline: 2.4857x; 2.4857x over previous
#include <cuda_runtime.h>

// Involution: B=4, H=W=56, C=256, Cr=64, G=16, Cg=16, K=7, pad=3, stride=1
// Fully fused. Round 2: LDS-minimized (kernel was L1tex-bound at 75.4%).

#define HH 56
#define WWD 56
#define CC 256
#define CR 64
#define NG 16
#define CGC 16
#define KS 7
#define KKT 49
#define THT 4
#define TWT 8
#define NPX 32
#define NT 256
#define HALO_H 10
#define HALO_W 14
#define NPOS 140
#define KGP 52      // kg row pad (float4-aligned, conflict-free p-stride)
#define WTP 68      // wsgT row pad
#define RSP 68      // rs row pad (stride 64 was 5-way bank conflict in B3)

struct SmemT {
    union {
        struct {
            float xs[NPX][CC];      // 32 KB  x tile, all channels
            float ws[64][CR];       // 16 KB  w_reduce chunk (64 rows)
        } a;
        struct {
            float wsgT[2][KKT][WTP]; // 26.7 KB  w_span slices, transposed [k][d]
            float kg[2][NPX][KGP];   // 13.3 KB  kernels for 2 groups
            float xh[2][NPOS][CGC];  // 17.9 KB  halos for 2 groups
        } b;
    } u;
    float rs[NPX][RSP];             // 8.7 KB  post-BN-ReLU features
    float bnS[CR], bnB[CR];
    float bsh[2][KKT];
};

__global__ __launch_bounds__(NT)
void involution_fused_kernel(
    const float* __restrict__ x,
    const float* __restrict__ w_reduce,
    const float* __restrict__ gamma,
    const float* __restrict__ beta,
    const float* __restrict__ mean,
    const float* __restrict__ var,
    const float* __restrict__ w_span,
    const float* __restrict__ b_span,
    float* __restrict__ out)
{
    extern __shared__ __align__(16) unsigned char smem_raw[];
    SmemT& s = *reinterpret_cast<SmemT*>(smem_raw);

    const int t  = threadIdx.x;
    const int w0 = blockIdx.x * TWT;
    const int h0 = blockIdx.y * THT;
    const int bb = blockIdx.z;

    if (t < CR) {
        float sc = gamma[t] * rsqrtf(var[t] + 1e-3f);
        s.bnS[t] = sc;
        s.bnB[t] = beta[t] - mean[t] * sc;
    }

    // ---------------- A1: stage x tile (32 px x 256 ch) ----------------
    for (int i = t; i < NPX * (CC / 4); i += NT) {
        int p  = i >> 6;
        int c4 = i & 63;
        int h = h0 + (p >> 3);
        int w = w0 + (p & 7);
        *(float4*)&s.u.a.xs[p][c4 * 4] =
            *(const float4*)&x[(((size_t)bb * HH + h) * WWD + w) * CC + c4 * 4];
    }
    __syncthreads();

    // ---------------- A2: r = xs @ w_reduce -> BN -> ReLU ----------------
    {
        const int pgrp = t >> 4;
        const int p0 = pgrp * 2, p1 = p0 + 1;
        const int d0 = (t & 15) * 4;
        float acc0[4] = {0.f, 0.f, 0.f, 0.f};
        float acc1[4] = {0.f, 0.f, 0.f, 0.f};

        for (int cb = 0; cb < 4; ++cb) {            // 4 chunks of 64 K-rows
            for (int i = t; i < 64 * 16; i += NT) {
                int row = i >> 4, d4 = i & 15;
                *(float4*)&s.u.a.ws[row][d4 * 4] =
                    *(const float4*)&w_reduce[(size_t)(cb * 64 + row) * CR + d4 * 4];
            }
            __syncthreads();
            #pragma unroll 4
            for (int c4 = 0; c4 < 16; ++c4) {
                float4 a0 = *(float4*)&s.u.a.xs[p0][cb * 64 + c4 * 4];
                float4 a1 = *(float4*)&s.u.a.xs[p1][cb * 64 + c4 * 4];
                float4 wr0 = *(float4*)&s.u.a.ws[c4 * 4 + 0][d0];
                float4 wr1 = *(float4*)&s.u.a.ws[c4 * 4 + 1][d0];
                float4 wr2 = *(float4*)&s.u.a.ws[c4 * 4 + 2][d0];
                float4 wr3 = *(float4*)&s.u.a.ws[c4 * 4 + 3][d0];
                acc0[0] += a0.x*wr0.x + a0.y*wr1.x + a0.z*wr2.x + a0.w*wr3.x;
                acc0[1] += a0.x*wr0.y + a0.y*wr1.y + a0.z*wr2.y + a0.w*wr3.y;
                acc0[2] += a0.x*wr0.z + a0.y*wr1.z + a0.z*wr2.z + a0.w*wr3.z;
                acc0[3] += a0.x*wr0.w + a0.y*wr1.w + a0.z*wr2.w + a0.w*wr3.w;
                acc1[0] += a1.x*wr0.x + a1.y*wr1.x + a1.z*wr2.x + a1.w*wr3.x;
                acc1[1] += a1.x*wr0.y + a1.y*wr1.y + a1.z*wr2.y + a1.w*wr3.y;
                acc1[2] += a1.x*wr0.z + a1.y*wr1.z + a1.z*wr2.z + a1.w*wr3.z;
                acc1[3] += a1.x*wr0.w + a1.y*wr1.w + a1.z*wr2.w + a1.w*wr3.w;
            }
            __syncthreads();
        }
        #pragma unroll
        for (int j = 0; j < 4; ++j) {
            int d = d0 + j;
            s.rs[p0][d] = fmaxf(acc0[j] * s.bnS[d] + s.bnB[d], 0.f);
            s.rs[p1][d] = fmaxf(acc1[j] * s.bnS[d] + s.bnB[d], 0.f);
        }
    }
    __syncthreads();

    // ---------------- B: 8 iterations, 2 groups each ----------------
    for (int gp = 0; gp < 8; ++gp) {
        const int gA = gp * 2;

        // B1: halos for 2 groups
        for (int i = t; i < 2 * NPOS * 4; i += NT) {
            int g = i / (NPOS * 4);
            int rem = i - g * (NPOS * 4);
            int pos = rem >> 2, q = rem & 3;
            int hh_ = pos / HALO_W, ww_ = pos - hh_ * HALO_W;
            int h = h0 + hh_ - 3, w = w0 + ww_ - 3;
            float4 v = make_float4(0.f, 0.f, 0.f, 0.f);
            if (h >= 0 && h < HH && w >= 0 && w < WWD)
                v = *(const float4*)&x[(((size_t)bb * HH + h) * WWD + w) * CC
                                       + (gA + g) * CGC + q * 4];
            *(float4*)&s.u.b.xh[g][pos][q * 4] = v;
        }
        // B2: stage w_span slices transposed
        for (int i = t; i < CR * 2 * KKT; i += NT) {   // 6272
            int d = i / 98;
            int e = i - d * 98;
            int g = e / KKT;
            int k = e - g * KKT;
            s.u.b.wsgT[g][k][d] =
                w_span[(size_t)d * (KKT * NG) + (gA + g) * KKT + k];
        }
        if (t < 2 * KKT) {
            int g = t / KKT, k = t - g * KKT;
            s.bsh[g][k] = b_span[(gA + g) * KKT + k];
        }
        __syncthreads();

        // B3: kg = rs @ wsgT^T + bias   (2 groups, 2 px & 7 taps per thread)
        if (t < 224) {
            int g = t / 112;
            int r = t - g * 112;
            int pp = r / 7;
            int k0 = (r - pp * 7) * 7;
            int pA = pp * 2, pB = pA + 1;
            float acc[2][7];
            #pragma unroll
            for (int j = 0; j < 7; ++j) {
                acc[0][j] = s.bsh[g][k0 + j];
                acc[1][j] = s.bsh[g][k0 + j];
            }
            #pragma unroll 4
            for (int d4 = 0; d4 < 16; ++d4) {
                float4 ra = *(float4*)&s.rs[pA][d4 * 4];
                float4 rb = *(float4*)&s.rs[pB][d4 * 4];
                #pragma unroll
                for (int j = 0; j < 7; ++j) {
                    float4 w4 = *(float4*)&s.u.b.wsgT[g][k0 + j][d4 * 4];
                    acc[0][j] += ra.x*w4.x + ra.y*w4.y + ra.z*w4.z + ra.w*w4.w;
                    acc[1][j] += rb.x*w4.x + rb.y*w4.y + rb.z*w4.z + rb.w*w4.w;
                }
            }
            #pragma unroll
            for (int j = 0; j < 7; ++j) {
                s.u.b.kg[g][pA][k0 + j] = acc[0][j];
                s.u.b.kg[g][pB][k0 + j] = acc[1][j];
            }
        }
        __syncthreads();

        // B4: depthwise 49-tap gather; kg cached in registers, float4 channels
        {
            int g  = t >> 7;
            int r  = t & 127;
            int p  = r >> 2;
            int c4 = r & 3;
            int py = p >> 3, px = p & 7;
            float kga[52];
            #pragma unroll
            for (int i = 0; i < 13; ++i) {
                float4 v = *(float4*)&s.u.b.kg[g][p][i * 4];
                kga[4*i+0] = v.x; kga[4*i+1] = v.y;
                kga[4*i+2] = v.z; kga[4*i+3] = v.w;
            }
            float4 acc = make_float4(0.f, 0.f, 0.f, 0.f);
            #pragma unroll
            for (int kh = 0; kh < KS; ++kh) {
                #pragma unroll
                for (int kw = 0; kw < KS; ++kw) {
                    float kv = kga[kh * KS + kw];
                    float4 xv = *(float4*)&s.u.b.xh[g][(py + kh) * HALO_W + (px + kw)][c4 * 4];
                    acc.x += kv * xv.x; acc.y += kv * xv.y;
                    acc.z += kv * xv.z; acc.w += kv * xv.w;
                }
            }
            *(float4*)&out[(((size_t)bb * HH + (h0 + py)) * WWD + (w0 + px)) * CC
                           + (gA + g) * CGC + c4 * 4] = acc;
        }
        __syncthreads();
    }
}

extern "C" void kernel_launch(void* const* d_in, const int* in_sizes, int n_in,
                              void* d_out, int out_size) {
    (void)in_sizes; (void)n_in; (void)out_size;
    const float* x        = (const float*)d_in[0];
    const float* w_reduce = (const float*)d_in[1];
    const float* gamma    = (const float*)d_in[2];
    const float* beta     = (const float*)d_in[3];
    const float* mean     = (const float*)d_in[4];
    const float* var      = (const float*)d_in[5];
    const float* w_span   = (const float*)d_in[6];
    const float* b_span   = (const float*)d_in[7];
    float* out = (float*)d_out;

    cudaFuncSetAttribute(involution_fused_kernel,
                         cudaFuncAttributeMaxDynamicSharedMemorySize,
                         (int)sizeof(SmemT));

    dim3 grid(WWD / TWT, HH / THT, 4);   // (7, 14, 4) = 392 CTAs
    involution_fused_kernel<<<grid, NT, sizeof(SmemT)>>>(
        x, w_reduce, gamma, beta, mean, var, w_span, b_span, out);
}

// round 5
// speedup vs baseline: 2.7044x; 1.0880x over previous
#include <cuda_runtime.h>

// Involution: B=4, H=W=56, C=256, Cr=64, G=16, Cg=16, K=7, pad=3
// Round 4: R3 structure with alignment fixes (xs pad 68, 16B-aligned globals).

#define HH 56
#define WWD 56
#define CC 256
#define CR 64
#define NG 16
#define CGC 16
#define KKT 49
#define NPIXT 12544          // 4*56*56
#define HALO_W 14
#define NPOS 140             // 10*14
#define XHP 24               // xh row pad (floats)
#define KGPAD 50             // kg row pad
#define RSP 68               // rs row pad

__device__ __align__(16) float g_wsT[NG * KKT * CR];   // [g][k][d]
__device__ __align__(16) float g_wr2[CC * CR];         // BN-folded w_reduce
__device__ __align__(16) float g_bias2[CR];            // BN-folded bias
__device__ __align__(16) float g_rs[(size_t)NPIXT * CR];

// ---------------------------------------------------------------- prep
__global__ void prep_kernel(const float* __restrict__ wr,
                            const float* __restrict__ gamma,
                            const float* __restrict__ beta,
                            const float* __restrict__ mean,
                            const float* __restrict__ var,
                            const float* __restrict__ wspan) {
    int t = blockIdx.x * blockDim.x + threadIdx.x;
    int nth = gridDim.x * blockDim.x;
    for (int i = t; i < NG * KKT * CR; i += nth) {
        int d = i & 63, gk = i >> 6;
        g_wsT[i] = wspan[(size_t)d * (KKT * NG) + gk];
    }
    for (int i = t; i < CC * CR; i += nth) {
        int d = i & 63;
        float s = gamma[d] * rsqrtf(var[d] + 1e-3f);
        g_wr2[i] = wr[i] * s;
    }
    for (int i = t; i < CR; i += nth) {
        float s = gamma[i] * rsqrtf(var[i] + 1e-3f);
        g_bias2[i] = beta[i] - mean[i] * s;
    }
}

// ---------------------------------------------------------------- rs GEMM
// rs[pix][d] = relu(sum_c x[pix][c]*wr2[c][d] + bias2[d]);  12544 x 64, K=256
#define RPX 128
struct SmemR {
    float xs[RPX][68];    // 34816 B  (pad 68: 272 B rows, 16B-aligned)
    float ws[CR][CR];     // 16384 B
};

__global__ __launch_bounds__(256)
void rs_kernel(const float* __restrict__ x) {
    extern __shared__ __align__(16) float smr[];
    SmemR& s = *reinterpret_cast<SmemR*>(smr);
    const int t = threadIdx.x;
    const int pix0 = blockIdx.x * RPX;
    const int dt = t & 15, mt = t >> 4;
    const int d0 = dt * 4;

    float4 acc[8];
    #pragma unroll
    for (int i = 0; i < 8; ++i) acc[i] = make_float4(0.f, 0.f, 0.f, 0.f);

    for (int cb = 0; cb < 4; ++cb) {
        for (int i = t; i < RPX * 16; i += 256) {
            int p = i >> 4, c = i & 15;
            *(float4*)&s.xs[p][c * 4] =
                __ldg((const float4*)&x[(size_t)(pix0 + p) * CC + cb * 64 + c * 4]);
        }
        for (int i = t; i < 64 * 16; i += 256) {
            int r = i >> 4, c = i & 15;
            *(float4*)&s.ws[r][c * 4] =
                __ldg((const float4*)&g_wr2[(size_t)(cb * 64 + r) * CR + c * 4]);
        }
        __syncthreads();
        #pragma unroll 4
        for (int c4 = 0; c4 < 16; ++c4) {
            float4 w0 = *(float4*)&s.ws[c4 * 4 + 0][d0];
            float4 w1 = *(float4*)&s.ws[c4 * 4 + 1][d0];
            float4 w2 = *(float4*)&s.ws[c4 * 4 + 2][d0];
            float4 w3 = *(float4*)&s.ws[c4 * 4 + 3][d0];
            #pragma unroll
            for (int i = 0; i < 8; ++i) {
                float4 a = *(float4*)&s.xs[mt * 8 + i][c4 * 4];
                acc[i].x += a.x*w0.x + a.y*w1.x + a.z*w2.x + a.w*w3.x;
                acc[i].y += a.x*w0.y + a.y*w1.y + a.z*w2.y + a.w*w3.y;
                acc[i].z += a.x*w0.z + a.y*w1.z + a.z*w2.z + a.w*w3.z;
                acc[i].w += a.x*w0.w + a.y*w1.w + a.z*w2.w + a.w*w3.w;
            }
        }
        __syncthreads();
    }
    float4 b = __ldg((const float4*)&g_bias2[d0]);
    #pragma unroll
    for (int i = 0; i < 8; ++i) {
        float4 v;
        v.x = fmaxf(acc[i].x + b.x, 0.f);
        v.y = fmaxf(acc[i].y + b.y, 0.f);
        v.z = fmaxf(acc[i].z + b.z, 0.f);
        v.w = fmaxf(acc[i].w + b.w, 0.f);
        *(float4*)&g_rs[(size_t)(pix0 + mt * 8 + i) * CR + d0] = v;
    }
}

// ---------------------------------------------------------------- main
struct SmemM {
    float rs[32][RSP];            //  8704 B
    float xh[2][2][NPOS][XHP];    // 53760 B  (double-buffered halos, 2 groups each)
    float kg[2][32][KGPAD];       // 12800 B
};                                // 75264 B total

__device__ __forceinline__ void halo_load(SmemM& s, const float* __restrict__ x,
                                          int gA, int buf, int tl, int nthr,
                                          int h0, int w0, int bb) {
    for (int i = tl; i < 2 * NPOS * 4; i += nthr) {
        int g = i / (NPOS * 4);
        int rem = i - g * (NPOS * 4);
        int pos = rem >> 2, q = rem & 3;
        int hh = pos / HALO_W, ww = pos - hh * HALO_W;
        int h = h0 + hh - 3, w = w0 + ww - 3;
        float4 v = make_float4(0.f, 0.f, 0.f, 0.f);
        if (h >= 0 && h < HH && w >= 0 && w < WWD)
            v = __ldg((const float4*)&x[(((size_t)bb * HH + h) * WWD + w) * CC
                                        + (gA + g) * CGC + q * 4]);
        *(float4*)&s.xh[buf][g][pos][q * 4] = v;
    }
}

__global__ __launch_bounds__(256)
void inv_main(const float* __restrict__ x,
              const float* __restrict__ b_span,
              float* __restrict__ out) {
    extern __shared__ __align__(16) float smf[];
    SmemM& s = *reinterpret_cast<SmemM*>(smf);
    const int t = threadIdx.x;
    const int w0 = blockIdx.x * 8, h0 = blockIdx.y * 4, bb = blockIdx.z;
    const size_t pixbase = ((size_t)bb * HH + h0) * WWD + w0;

    // stage rs tile (32 px x 64 d)
    for (int i = t; i < 512; i += 256) {
        int p = i >> 4, c = i & 15;
        int py = p >> 3, pxl = p & 7;
        size_t pix = pixbase + (size_t)py * WWD + pxl;
        *(float4*)&s.rs[p][c * 4] = __ldg((const float4*)&g_rs[pix * CR + c * 4]);
    }
    // prologue: halo for group-pair 0
    halo_load(s, x, 0, 0, t, 256, h0, w0, bb);
    __syncthreads();

    for (int gp = 0; gp < 8; ++gp) {
        const int buf = gp & 1;
        const int gA = gp * 2;

        if (t < 112) {
            // B3: kg[g][p][k] = rs[p][:] . wsT[g][k][:] + b_span
            const int g = t / 56, r = t - g * 56;
            const int quad = r & 7, kgi = r >> 3;     // lanes 0-7: quads (bcast w)
            const int k0 = kgi * 7;
            const float* wrow = &g_wsT[(size_t)((gA + g) * KKT + k0) * CR];
            float acc[4][7];
            #pragma unroll
            for (int j = 0; j < 7; ++j) {
                float bv = __ldg(&b_span[(gA + g) * KKT + k0 + j]);
                acc[0][j] = bv; acc[1][j] = bv; acc[2][j] = bv; acc[3][j] = bv;
            }
            #pragma unroll 2
            for (int d4 = 0; d4 < 16; ++d4) {
                float4 ra0 = *(float4*)&s.rs[quad +  0][d4 * 4];
                float4 ra1 = *(float4*)&s.rs[quad +  8][d4 * 4];
                float4 ra2 = *(float4*)&s.rs[quad + 16][d4 * 4];
                float4 ra3 = *(float4*)&s.rs[quad + 24][d4 * 4];
                #pragma unroll
                for (int j = 0; j < 7; ++j) {
                    float4 w4 = __ldg((const float4*)&wrow[j * CR + d4 * 4]);
                    acc[0][j] += ra0.x*w4.x + ra0.y*w4.y + ra0.z*w4.z + ra0.w*w4.w;
                    acc[1][j] += ra1.x*w4.x + ra1.y*w4.y + ra1.z*w4.z + ra1.w*w4.w;
                    acc[2][j] += ra2.x*w4.x + ra2.y*w4.y + ra2.z*w4.z + ra2.w*w4.w;
                    acc[3][j] += ra3.x*w4.x + ra3.y*w4.y + ra3.z*w4.z + ra3.w*w4.w;
                }
            }
            #pragma unroll
            for (int i = 0; i < 4; ++i)
                #pragma unroll
                for (int j = 0; j < 7; ++j)
                    s.kg[g][quad + 8 * i][k0 + j] = acc[i][j];
        } else if (gp < 7) {
            // prefetch next group-pair's halo into the other buffer
            halo_load(s, x, gA + 2, buf ^ 1, t - 112, 144, h0, w0, bb);
        }
        __syncthreads();

        if (t < 128) {
            // B4: depthwise 49-tap, 2 px x 4 ch per thread, sliding row window
            const int g = t >> 6, r = t & 63;
            const int pp = r >> 2, c4 = r & 3;
            const int px0 = pp * 2, py = px0 >> 3, pxl = px0 & 7;
            float4 a0 = make_float4(0.f, 0.f, 0.f, 0.f);
            float4 a1 = make_float4(0.f, 0.f, 0.f, 0.f);
            #pragma unroll
            for (int kh = 0; kh < 7; ++kh) {
                float4 xw[8];
                const int rb = (py + kh) * HALO_W + pxl;
                #pragma unroll
                for (int cc = 0; cc < 8; ++cc)
                    xw[cc] = *(float4*)&s.xh[buf][g][rb + cc][c4 * 4];
                #pragma unroll
                for (int kw = 0; kw < 7; ++kw) {
                    float k0v = s.kg[g][px0][kh * 7 + kw];
                    float k1v = s.kg[g][px0 + 1][kh * 7 + kw];
                    a0.x += k0v * xw[kw].x;     a0.y += k0v * xw[kw].y;
                    a0.z += k0v * xw[kw].z;     a0.w += k0v * xw[kw].w;
                    a1.x += k1v * xw[kw + 1].x; a1.y += k1v * xw[kw + 1].y;
                    a1.z += k1v * xw[kw + 1].z; a1.w += k1v * xw[kw + 1].w;
                }
            }
            size_t o = (pixbase + (size_t)py * WWD + pxl) * CC + (gA + g) * CGC + c4 * 4;
            *(float4*)&out[o] = a0;
            *(float4*)&out[o + CC] = a1;
        }
        __syncthreads();
    }
}

// ---------------------------------------------------------------- launch
extern "C" void kernel_launch(void* const* d_in, const int* in_sizes, int n_in,
                              void* d_out, int out_size) {
    (void)in_sizes; (void)n_in; (void)out_size;
    const float* x        = (const float*)d_in[0];
    const float* w_reduce = (const float*)d_in[1];
    const float* gamma    = (const float*)d_in[2];
    const float* beta     = (const float*)d_in[3];
    const float* mean     = (const float*)d_in[4];
    const float* var      = (const float*)d_in[5];
    const float* w_span   = (const float*)d_in[6];
    const float* b_span   = (const float*)d_in[7];
    float* out = (float*)d_out;

    cudaFuncSetAttribute(rs_kernel, cudaFuncAttributeMaxDynamicSharedMemorySize,
                         (int)sizeof(SmemR));
    cudaFuncSetAttribute(inv_main, cudaFuncAttributeMaxDynamicSharedMemorySize,
                         (int)sizeof(SmemM));

    prep_kernel<<<64, 256>>>(w_reduce, gamma, beta, mean, var, w_span);
    rs_kernel<<<NPIXT / RPX, 256, sizeof(SmemR)>>>(x);
    dim3 grid(WWD / 8, HH / 4, 4);
    inv_main<<<grid, 256, sizeof(SmemM)>>>(x, b_span, out);
}